// round 2
// baseline (speedup 1.0000x reference)
#include <cuda_runtime.h>
#include <cuda_bf16.h>
#include <math.h>

// ---------------- device scratch (no allocations allowed) ----------------
#define MAXN 100000
#define MAXE 3400000

__device__ int   g_cnt[MAXN];
__device__ int   g_rowptr[MAXN + 1];
__device__ int   g_wtmp[MAXN];
__device__ int   g_col[MAXE];
__device__ float g_dinv[MAXN];
__device__ float g_z[MAXN * 16];   // dinv-scaled x@W1
__device__ float g_h[MAXN * 16];   // hidden state
__device__ float g_u[MAXN * 8];    // dinv-scaled h@W2 (padded to 8)

// ---------------- CSR build ----------------
__global__ void zero_cnt_k(int N) {
    int i = blockIdx.x * blockDim.x + threadIdx.x;
    if (i < N) g_cnt[i] = 0;
}

__global__ void count_k(const int* __restrict__ ei, int E, int N) {
    int e = blockIdx.x * blockDim.x + threadIdx.x;
    if (e < E) {
        int d = ei[E + e];
        if (d >= 0 && d < N) atomicAdd(&g_cnt[d], 1);
    }
}

// single-block exclusive scan of g_cnt -> g_rowptr/g_wtmp, plus dinv
__global__ void scan_k(int N, int E) {
    __shared__ int ssum[1024];
    int t = threadIdx.x;
    int CH = (N + 1023) >> 10;
    int beg = t * CH;
    int end = beg + CH; if (end > N) end = N;
    int s = 0;
    for (int i = beg; i < end; ++i) s += g_cnt[i];
    ssum[t] = s;
    __syncthreads();
    for (int off = 1; off < 1024; off <<= 1) {
        int v = (t >= off) ? ssum[t - off] : 0;
        __syncthreads();
        ssum[t] += v;
        __syncthreads();
    }
    int run = (t > 0) ? ssum[t - 1] : 0;
    for (int i = beg; i < end; ++i) {
        g_rowptr[i] = run;
        g_wtmp[i]   = run;
        g_dinv[i]   = rsqrtf((float)(g_cnt[i] + 1));
        run += g_cnt[i];
    }
    if (beg < N && end == N) g_rowptr[N] = run;  // == E (minus any dropped)
}

__global__ void scatter_k(const int* __restrict__ ei, int E, int N) {
    int e = blockIdx.x * blockDim.x + threadIdx.x;
    if (e < E) {
        int s = ei[e];
        int d = ei[E + e];
        if (d >= 0 && d < N && s >= 0 && s < N) {
            int pos = atomicAdd(&g_wtmp[d], 1);
            g_col[pos] = s;
        }
    }
}

// ---------------- GEMM1: z = dinv * (x @ W1)  [N,512]x[512,16] ----------------
// block = 128 threads, 32 nodes per block; lane = node, warp og -> 4 outputs
__global__ void gemm1_k(const float* __restrict__ x, const float* __restrict__ W1, int N) {
    __shared__ float Ws[512 * 16];        // 32 KB
    __shared__ float xs[32 * 65];         // 8.3 KB, stride 65 -> conflict-free
    int tid  = threadIdx.x;
    int lane = tid & 31;
    int og   = tid >> 5;                  // 0..3
    int n0   = blockIdx.x * 32;

    const float4* Wg4 = (const float4*)W1;
    float4* Ws4 = (float4*)Ws;
    for (int i = tid; i < 512 * 16 / 4; i += 128) Ws4[i] = Wg4[i];

    float a0 = 0.f, a1 = 0.f, a2 = 0.f, a3 = 0.f;

    for (int kt = 0; kt < 512; kt += 64) {
        __syncthreads();
        // load 32 rows x 64 cols (512 float4s), 4 per thread
        for (int i = tid; i < 512; i += 128) {
            int r  = i >> 4;
            int c4 = i & 15;
            float4 v = make_float4(0.f, 0.f, 0.f, 0.f);
            if (n0 + r < N)
                v = *(const float4*)&x[(size_t)(n0 + r) * 512 + kt + c4 * 4];
            int b = r * 65 + c4 * 4;
            xs[b] = v.x; xs[b + 1] = v.y; xs[b + 2] = v.z; xs[b + 3] = v.w;
        }
        __syncthreads();
        const float* xr = &xs[lane * 65];
#pragma unroll 16
        for (int k = 0; k < 64; ++k) {
            float  xv = xr[k];
            float4 w  = Ws4[(kt + k) * 4 + og];
            a0 = fmaf(xv, w.x, a0);
            a1 = fmaf(xv, w.y, a1);
            a2 = fmaf(xv, w.z, a2);
            a3 = fmaf(xv, w.w, a3);
        }
    }
    int n = n0 + lane;
    if (n < N) {
        float d = g_dinv[n];
        float4 o = make_float4(a0 * d, a1 * d, a2 * d, a3 * d);
        *(float4*)&g_z[(size_t)n * 16 + og * 4] = o;
    }
}

// ---------------- Aggregation 1: h = relu(dinv*(sum z[col] + z[i]) + b1) ----------------
// 16 lanes per node, 256 threads -> 16 nodes / block
__global__ void agg1_k(const float* __restrict__ b1, int N) {
    int tid = threadIdx.x;
    int gi  = tid >> 4;
    int l   = tid & 15;
    int node = blockIdx.x * 16 + gi;
    if (node >= N) return;

    int beg = g_rowptr[node];
    int end = g_rowptr[node + 1];
    float acc = 0.f;
    int p = beg;
    for (; p + 4 <= end; p += 4) {
        int s0 = g_col[p], s1 = g_col[p + 1], s2 = g_col[p + 2], s3 = g_col[p + 3];
        acc += g_z[(size_t)s0 * 16 + l];
        acc += g_z[(size_t)s1 * 16 + l];
        acc += g_z[(size_t)s2 * 16 + l];
        acc += g_z[(size_t)s3 * 16 + l];
    }
    for (; p < end; ++p) acc += g_z[(size_t)g_col[p] * 16 + l];

    float v = g_dinv[node] * (acc + g_z[(size_t)node * 16 + l]) + b1[l];
    g_h[(size_t)node * 16 + l] = fmaxf(v, 0.f);
}

// ---------------- 10 hops (per-node, fused) + final W2 + dinv scale ----------------
__global__ void hops_final_k(const float* __restrict__ Wl, const float* __restrict__ bl,
                             const float* __restrict__ W2, int N) {
    __shared__ float Wls[16 * 16];
    __shared__ float W2s[16 * 8];
    __shared__ float bls[16];
    int tid = threadIdx.x;
    if (tid < 256) Wls[tid] = Wl[tid];
    if (tid < 16 * 8) W2s[tid] = 0.f;
    __syncthreads();
    if (tid < 16 * 7) W2s[(tid / 7) * 8 + (tid % 7)] = W2[tid];
    if (tid < 16) bls[tid] = bl[tid];
    __syncthreads();

    int n = blockIdx.x * blockDim.x + tid;
    if (n >= N) return;

    float h[16];
    const float4* hg = (const float4*)&g_h[(size_t)n * 16];
#pragma unroll
    for (int q = 0; q < 4; ++q) {
        float4 v = hg[q];
        h[q * 4 + 0] = v.x; h[q * 4 + 1] = v.y; h[q * 4 + 2] = v.z; h[q * 4 + 3] = v.w;
    }

    const float4* Wl4 = (const float4*)Wls;
#pragma unroll 1
    for (int it = 0; it < 10; ++it) {
        float nh[16];
#pragma unroll
        for (int o = 0; o < 16; ++o) nh[o] = 0.f;
#pragma unroll
        for (int k = 0; k < 16; ++k) {
            float hv = h[k];
#pragma unroll
            for (int o4 = 0; o4 < 4; ++o4) {
                float4 w = Wl4[k * 4 + o4];
                nh[o4 * 4 + 0] = fmaf(hv, w.x, nh[o4 * 4 + 0]);
                nh[o4 * 4 + 1] = fmaf(hv, w.y, nh[o4 * 4 + 1]);
                nh[o4 * 4 + 2] = fmaf(hv, w.z, nh[o4 * 4 + 2]);
                nh[o4 * 4 + 3] = fmaf(hv, w.w, nh[o4 * 4 + 3]);
            }
        }
#pragma unroll
        for (int o = 0; o < 16; ++o)
            h[o] = 0.1f * fmaxf(nh[o] + bls[o], 0.f) + 0.9f * h[o];
    }

    // u = dinv * (h @ W2), padded to 8
    float u[8];
#pragma unroll
    for (int o = 0; o < 8; ++o) u[o] = 0.f;
#pragma unroll
    for (int k = 0; k < 16; ++k) {
        float hv = h[k];
#pragma unroll
        for (int o = 0; o < 7; ++o)
            u[o] = fmaf(hv, W2s[k * 8 + o], u[o]);
    }
    float d = g_dinv[n];
    float4 u0 = make_float4(u[0] * d, u[1] * d, u[2] * d, u[3] * d);
    float4 u1 = make_float4(u[4] * d, u[5] * d, u[6] * d, 0.f);
    float4* ug = (float4*)&g_u[(size_t)n * 8];
    ug[0] = u0; ug[1] = u1;
}

// ---------------- Aggregation 2 + bias + log_softmax ----------------
// 8 lanes per node, 256 threads -> 32 nodes / block
__global__ void agg2_k(const float* __restrict__ b2, float* __restrict__ out, int N) {
    int tid = threadIdx.x;
    int gi  = tid >> 3;
    int l   = tid & 7;
    int node = blockIdx.x * 32 + gi;
    int nc = (node < N) ? node : 0;  // clamp so all lanes stay live for shfl

    int beg = g_rowptr[nc];
    int end = g_rowptr[nc + 1];
    float acc = 0.f;
    int p = beg;
    for (; p + 4 <= end; p += 4) {
        int s0 = g_col[p], s1 = g_col[p + 1], s2 = g_col[p + 2], s3 = g_col[p + 3];
        acc += g_u[(size_t)s0 * 8 + l];
        acc += g_u[(size_t)s1 * 8 + l];
        acc += g_u[(size_t)s2 * 8 + l];
        acc += g_u[(size_t)s3 * 8 + l];
    }
    for (; p < end; ++p) acc += g_u[(size_t)g_col[p] * 8 + l];

    float v = g_dinv[nc] * (acc + g_u[(size_t)nc * 8 + l]) + ((l < 7) ? b2[l] : 0.f);

    // log_softmax over lanes 0..6 within the 8-lane group
    float vm = (l < 7) ? v : -INFINITY;
    vm = fmaxf(vm, __shfl_xor_sync(0xFFFFFFFFu, vm, 1));
    vm = fmaxf(vm, __shfl_xor_sync(0xFFFFFFFFu, vm, 2));
    vm = fmaxf(vm, __shfl_xor_sync(0xFFFFFFFFu, vm, 4));
    float e = (l < 7) ? expf(v - vm) : 0.f;
    float s = e;
    s += __shfl_xor_sync(0xFFFFFFFFu, s, 1);
    s += __shfl_xor_sync(0xFFFFFFFFu, s, 2);
    s += __shfl_xor_sync(0xFFFFFFFFu, s, 4);
    float r = v - vm - logf(s);

    if (node < N && l < 7) out[(size_t)node * 7 + l] = r;
}

// ---------------- launch ----------------
extern "C" void kernel_launch(void* const* d_in, const int* in_sizes, int n_in,
                              void* d_out, int out_size) {
    const float* x  = (const float*)d_in[0];
    const int*   ei = (const int*)d_in[1];    // int32: JAX default (x64 disabled)
    const float* W1 = (const float*)d_in[2];
    const float* b1 = (const float*)d_in[3];
    const float* Wl = (const float*)d_in[4];
    const float* bl = (const float*)d_in[5];
    const float* W2 = (const float*)d_in[6];
    const float* b2 = (const float*)d_in[7];
    float* out = (float*)d_out;

    int N = in_sizes[0] / 512;
    int E = in_sizes[1] / 2;

    zero_cnt_k<<<(N + 255) / 256, 256>>>(N);
    count_k<<<(E + 255) / 256, 256>>>(ei, E, N);
    scan_k<<<1, 1024>>>(N, E);
    scatter_k<<<(E + 255) / 256, 256>>>(ei, E, N);
    gemm1_k<<<(N + 31) / 32, 128>>>(x, W1, N);
    agg1_k<<<(N + 15) / 16, 256>>>(b1, N);
    hops_final_k<<<(N + 255) / 256, 256>>>(Wl, bl, W2, N);
    agg2_k<<<(N + 31) / 32, 256>>>(b2, out, N);
}

// round 3
// speedup vs baseline: 1.9991x; 1.9991x over previous
#include <cuda_runtime.h>
#include <cuda_bf16.h>
#include <math.h>

// ---------------- device scratch (no allocations allowed) ----------------
#define MAXN 100000
#define MAXE 3400000
#define MAXB 128          // max scan blocks (ceil(100000/1024)=98)

__device__ int   g_cnt[MAXN];
__device__ int   g_rowptr[MAXN + 1];
__device__ int   g_wtmp[MAXN];
__device__ int   g_col[MAXE];
__device__ int   g_part[MAXB];
__device__ int   g_partoff[MAXB];
__device__ float g_dinv[MAXN];
__device__ float g_z[MAXN * 16];   // dinv-scaled x@W1
__device__ float g_h[MAXN * 16];   // hidden state
__device__ float g_u[MAXN * 8];    // dinv-scaled h@W2 (padded to 8)

// ---------------- CSR build ----------------
__global__ void zero_cnt_k(int N) {
    int i = blockIdx.x * blockDim.x + threadIdx.x;
    if (i < N) g_cnt[i] = 0;
}

// 4 edges per thread, int4 loads, 4 independent atomics in flight
__global__ void count_k(const int* __restrict__ ei, int E, int N) {
    int base = (blockIdx.x * blockDim.x + threadIdx.x) * 4;
    const int* dstp = ei + E;
    if (base + 3 < E) {
        int4 d4 = *(const int4*)&dstp[base];
        if ((unsigned)d4.x < (unsigned)N) atomicAdd(&g_cnt[d4.x], 1);
        if ((unsigned)d4.y < (unsigned)N) atomicAdd(&g_cnt[d4.y], 1);
        if ((unsigned)d4.z < (unsigned)N) atomicAdd(&g_cnt[d4.z], 1);
        if ((unsigned)d4.w < (unsigned)N) atomicAdd(&g_cnt[d4.w], 1);
    } else {
        for (int e = base; e < E; ++e) {
            int d = dstp[e];
            if ((unsigned)d < (unsigned)N) atomicAdd(&g_cnt[d], 1);
        }
    }
}

// pass A: per-block sums of g_cnt (1024 threads/block)
__global__ void partial_k(int N) {
    __shared__ int red[32];
    int tid = threadIdx.x;
    int lane = tid & 31, wid = tid >> 5;
    int i = blockIdx.x * 1024 + tid;
    int v = (i < N) ? g_cnt[i] : 0;
#pragma unroll
    for (int off = 16; off > 0; off >>= 1) v += __shfl_xor_sync(0xFFFFFFFFu, v, off);
    if (lane == 0) red[wid] = v;
    __syncthreads();
    if (wid == 0) {
        int s = red[lane];
#pragma unroll
        for (int off = 16; off > 0; off >>= 1) s += __shfl_xor_sync(0xFFFFFFFFu, s, off);
        if (lane == 0) g_part[blockIdx.x] = s;
    }
}

// pass B: scan the (<=128) partials, one block
__global__ void scanpart_k(int nb, int N) {
    __shared__ int sp[128];
    int t = threadIdx.x;
    int v = (t < nb) ? g_part[t] : 0;
    sp[t] = v;
    __syncthreads();
    for (int off = 1; off < 128; off <<= 1) {
        int a = (t >= off) ? sp[t - off] : 0;
        __syncthreads();
        sp[t] += a;
        __syncthreads();
    }
    if (t < nb) g_partoff[t] = sp[t] - v;   // exclusive
    if (t == nb - 1) g_rowptr[N] = sp[t];   // total edge count
}

// pass C: block-level scan + emit rowptr/wtmp/dinv
__global__ void emit_k(int N) {
    __shared__ int wsums[32];
    int tid = threadIdx.x;
    int lane = tid & 31, wid = tid >> 5;
    int i = blockIdx.x * 1024 + tid;
    int c = (i < N) ? g_cnt[i] : 0;
    int v = c;
#pragma unroll
    for (int off = 1; off < 32; off <<= 1) {
        int t = __shfl_up_sync(0xFFFFFFFFu, v, off);
        if (lane >= off) v += t;
    }
    if (lane == 31) wsums[wid] = v;
    __syncthreads();
    if (wid == 0) {
        int w = wsums[lane];
#pragma unroll
        for (int off = 1; off < 32; off <<= 1) {
            int t = __shfl_up_sync(0xFFFFFFFFu, w, off);
            if (lane >= off) w += t;
        }
        wsums[lane] = w;
    }
    __syncthreads();
    int add = (wid > 0) ? wsums[wid - 1] : 0;
    int excl = v - c + add + g_partoff[blockIdx.x];
    if (i < N) {
        g_rowptr[i] = excl;
        g_wtmp[i]   = excl;
        g_dinv[i]   = rsqrtf((float)(c + 1));
    }
}

__global__ void scatter_k(const int* __restrict__ ei, int E, int N) {
    int base = (blockIdx.x * blockDim.x + threadIdx.x) * 4;
    const int* dstp = ei + E;
    if (base + 3 < E) {
        int4 s4 = *(const int4*)&ei[base];
        int4 d4 = *(const int4*)&dstp[base];
        if ((unsigned)d4.x < (unsigned)N && (unsigned)s4.x < (unsigned)N)
            g_col[atomicAdd(&g_wtmp[d4.x], 1)] = s4.x;
        if ((unsigned)d4.y < (unsigned)N && (unsigned)s4.y < (unsigned)N)
            g_col[atomicAdd(&g_wtmp[d4.y], 1)] = s4.y;
        if ((unsigned)d4.z < (unsigned)N && (unsigned)s4.z < (unsigned)N)
            g_col[atomicAdd(&g_wtmp[d4.z], 1)] = s4.z;
        if ((unsigned)d4.w < (unsigned)N && (unsigned)s4.w < (unsigned)N)
            g_col[atomicAdd(&g_wtmp[d4.w], 1)] = s4.w;
    } else {
        for (int e = base; e < E; ++e) {
            int s = ei[e], d = dstp[e];
            if ((unsigned)d < (unsigned)N && (unsigned)s < (unsigned)N)
                g_col[atomicAdd(&g_wtmp[d], 1)] = s;
        }
    }
}

// ---------------- GEMM1: z = dinv * (x @ W1)  [N,512]x[512,16] ----------------
// one node per thread, 16 register accumulators, x streamed via LDG.128,
// W1 broadcast from smem. FMA-pipe bound.
__global__ void __launch_bounds__(128) gemm1_k(const float* __restrict__ x,
                                               const float* __restrict__ W1, int N) {
    __shared__ float4 Ws4[512 * 4];   // [k][o4], 32 KB
    int tid = threadIdx.x;
    const float4* Wg4 = (const float4*)W1;
    for (int i = tid; i < 2048; i += 128) Ws4[i] = Wg4[i];
    __syncthreads();

    int n = blockIdx.x * 128 + tid;
    if (n >= N) return;

    const float4* xr = (const float4*)(x + (size_t)n * 512);
    float acc[16];
#pragma unroll
    for (int o = 0; o < 16; ++o) acc[o] = 0.f;

#pragma unroll 4
    for (int k4 = 0; k4 < 128; ++k4) {
        float4 xv = xr[k4];
#pragma unroll
        for (int j = 0; j < 4; ++j) {
            float xk = (j == 0) ? xv.x : (j == 1) ? xv.y : (j == 2) ? xv.z : xv.w;
            int k = k4 * 4 + j;
#pragma unroll
            for (int o4 = 0; o4 < 4; ++o4) {
                float4 w = Ws4[k * 4 + o4];
                acc[o4 * 4 + 0] = fmaf(xk, w.x, acc[o4 * 4 + 0]);
                acc[o4 * 4 + 1] = fmaf(xk, w.y, acc[o4 * 4 + 1]);
                acc[o4 * 4 + 2] = fmaf(xk, w.z, acc[o4 * 4 + 2]);
                acc[o4 * 4 + 3] = fmaf(xk, w.w, acc[o4 * 4 + 3]);
            }
        }
    }

    float d = g_dinv[n];
    float4* zo = (float4*)&g_z[(size_t)n * 16];
#pragma unroll
    for (int o4 = 0; o4 < 4; ++o4)
        zo[o4] = make_float4(acc[o4 * 4 + 0] * d, acc[o4 * 4 + 1] * d,
                             acc[o4 * 4 + 2] * d, acc[o4 * 4 + 3] * d);
}

// ---------------- Aggregation 1: h = relu(dinv*(sum z[col] + z[i]) + b1) ----------------
// 4 lanes per node, float4 gathers; 256 threads -> 64 nodes/block
__global__ void agg1_k(const float* __restrict__ b1, int N) {
    int tid = threadIdx.x;
    int gi  = tid >> 2;
    int l   = tid & 3;
    int node = blockIdx.x * 64 + gi;
    if (node >= N) return;

    int beg = g_rowptr[node];
    int end = g_rowptr[node + 1];
    const float4* z4 = (const float4*)g_z;
    float4 acc = make_float4(0.f, 0.f, 0.f, 0.f);
    int p = beg;
    for (; p + 2 <= end; p += 2) {
        int s0 = g_col[p], s1 = g_col[p + 1];
        float4 a = z4[(size_t)s0 * 4 + l];
        float4 b = z4[(size_t)s1 * 4 + l];
        acc.x += a.x + b.x; acc.y += a.y + b.y;
        acc.z += a.z + b.z; acc.w += a.w + b.w;
    }
    if (p < end) {
        float4 a = z4[(size_t)g_col[p] * 4 + l];
        acc.x += a.x; acc.y += a.y; acc.z += a.z; acc.w += a.w;
    }
    float4 self = z4[(size_t)node * 4 + l];
    float di = g_dinv[node];
    float4 bb = ((const float4*)b1)[l];
    float4 o;
    o.x = fmaxf(fmaf(di, acc.x + self.x, bb.x), 0.f);
    o.y = fmaxf(fmaf(di, acc.y + self.y, bb.y), 0.f);
    o.z = fmaxf(fmaf(di, acc.z + self.z, bb.z), 0.f);
    o.w = fmaxf(fmaf(di, acc.w + self.w, bb.w), 0.f);
    ((float4*)g_h)[(size_t)node * 4 + l] = o;
}

// ---------------- 10 hops (per-node, fused) + final W2 + dinv scale ----------------
__global__ void hops_final_k(const float* __restrict__ Wl, const float* __restrict__ bl,
                             const float* __restrict__ W2, int N) {
    __shared__ float Wls[16 * 16];
    __shared__ float W2s[16 * 8];
    __shared__ float bls[16];
    int tid = threadIdx.x;
    if (tid < 256) Wls[tid] = Wl[tid];
    if (tid < 16 * 8) W2s[tid] = 0.f;
    __syncthreads();
    if (tid < 16 * 7) W2s[(tid / 7) * 8 + (tid % 7)] = W2[tid];
    if (tid < 16) bls[tid] = bl[tid];
    __syncthreads();

    int n = blockIdx.x * blockDim.x + tid;
    if (n >= N) return;

    float h[16];
    const float4* hg = (const float4*)&g_h[(size_t)n * 16];
#pragma unroll
    for (int q = 0; q < 4; ++q) {
        float4 v = hg[q];
        h[q * 4 + 0] = v.x; h[q * 4 + 1] = v.y; h[q * 4 + 2] = v.z; h[q * 4 + 3] = v.w;
    }

    const float4* Wl4 = (const float4*)Wls;
#pragma unroll 1
    for (int it = 0; it < 10; ++it) {
        float nh[16];
#pragma unroll
        for (int o = 0; o < 16; ++o) nh[o] = 0.f;
#pragma unroll
        for (int k = 0; k < 16; ++k) {
            float hv = h[k];
#pragma unroll
            for (int o4 = 0; o4 < 4; ++o4) {
                float4 w = Wl4[k * 4 + o4];
                nh[o4 * 4 + 0] = fmaf(hv, w.x, nh[o4 * 4 + 0]);
                nh[o4 * 4 + 1] = fmaf(hv, w.y, nh[o4 * 4 + 1]);
                nh[o4 * 4 + 2] = fmaf(hv, w.z, nh[o4 * 4 + 2]);
                nh[o4 * 4 + 3] = fmaf(hv, w.w, nh[o4 * 4 + 3]);
            }
        }
#pragma unroll
        for (int o = 0; o < 16; ++o)
            h[o] = 0.1f * fmaxf(nh[o] + bls[o], 0.f) + 0.9f * h[o];
    }

    float u[8];
#pragma unroll
    for (int o = 0; o < 8; ++o) u[o] = 0.f;
#pragma unroll
    for (int k = 0; k < 16; ++k) {
        float hv = h[k];
#pragma unroll
        for (int o = 0; o < 7; ++o)
            u[o] = fmaf(hv, W2s[k * 8 + o], u[o]);
    }
    float d = g_dinv[n];
    float4* ug = (float4*)&g_u[(size_t)n * 8];
    ug[0] = make_float4(u[0] * d, u[1] * d, u[2] * d, u[3] * d);
    ug[1] = make_float4(u[4] * d, u[5] * d, u[6] * d, 0.f);
}

// ---------------- Aggregation 2 + bias + log_softmax ----------------
// 2 lanes per node, float4 gathers, shfl softmax. 256 threads -> 128 nodes/block
__global__ void agg2_k(const float* __restrict__ b2, float* __restrict__ out, int N) {
    int tid = threadIdx.x;
    int gi  = tid >> 1;
    int l   = tid & 1;
    int node = blockIdx.x * 128 + gi;
    int nc = (node < N) ? node : (N - 1);   // clamp: keep lanes live for shfl

    int beg = g_rowptr[nc];
    int end = g_rowptr[nc + 1];
    const float4* u4 = (const float4*)g_u;
    float4 acc = make_float4(0.f, 0.f, 0.f, 0.f);
    int p = beg;
    for (; p + 2 <= end; p += 2) {
        int s0 = g_col[p], s1 = g_col[p + 1];
        float4 a = u4[(size_t)s0 * 2 + l];
        float4 b = u4[(size_t)s1 * 2 + l];
        acc.x += a.x + b.x; acc.y += a.y + b.y;
        acc.z += a.z + b.z; acc.w += a.w + b.w;
    }
    if (p < end) {
        float4 a = u4[(size_t)g_col[p] * 2 + l];
        acc.x += a.x; acc.y += a.y; acc.z += a.z; acc.w += a.w;
    }
    float4 self = u4[(size_t)nc * 2 + l];
    float di = g_dinv[nc];

    float4 v;
    if (l == 0) {
        v.x = fmaf(di, acc.x + self.x, b2[0]);
        v.y = fmaf(di, acc.y + self.y, b2[1]);
        v.z = fmaf(di, acc.z + self.z, b2[2]);
        v.w = fmaf(di, acc.w + self.w, b2[3]);
    } else {
        v.x = fmaf(di, acc.x + self.x, b2[4]);
        v.y = fmaf(di, acc.y + self.y, b2[5]);
        v.z = fmaf(di, acc.z + self.z, b2[6]);
        v.w = -INFINITY;   // padding lane
    }

    float m = fmaxf(fmaxf(v.x, v.y), fmaxf(v.z, v.w));
    m = fmaxf(m, __shfl_xor_sync(0xFFFFFFFFu, m, 1));
    float ex = expf(v.x - m) + expf(v.y - m) + expf(v.z - m) +
               ((l == 0) ? expf(v.w - m) : 0.f);
    float s = ex + __shfl_xor_sync(0xFFFFFFFFu, ex, 1);
    float lse = m + logf(s);

    if (node < N) {
        float* op = out + (size_t)node * 7;
        if (l == 0) {
            op[0] = v.x - lse; op[1] = v.y - lse;
            op[2] = v.z - lse; op[3] = v.w - lse;
        } else {
            op[4] = v.x - lse; op[5] = v.y - lse; op[6] = v.z - lse;
        }
    }
}

// ---------------- launch ----------------
extern "C" void kernel_launch(void* const* d_in, const int* in_sizes, int n_in,
                              void* d_out, int out_size) {
    const float* x  = (const float*)d_in[0];
    const int*   ei = (const int*)d_in[1];    // int32 (JAX default, x64 disabled)
    const float* W1 = (const float*)d_in[2];
    const float* b1 = (const float*)d_in[3];
    const float* Wl = (const float*)d_in[4];
    const float* bl = (const float*)d_in[5];
    const float* W2 = (const float*)d_in[6];
    const float* b2 = (const float*)d_in[7];
    float* out = (float*)d_out;

    int N = in_sizes[0] / 512;
    int E = in_sizes[1] / 2;
    int nb = (N + 1023) / 1024;               // scan blocks (98)
    int eb4 = ((E + 3) / 4 + 255) / 256;      // 4-edge-per-thread blocks

    zero_cnt_k<<<(N + 255) / 256, 256>>>(N);
    count_k<<<eb4, 256>>>(ei, E, N);
    partial_k<<<nb, 1024>>>(N);
    scanpart_k<<<1, 128>>>(nb, N);
    emit_k<<<nb, 1024>>>(N);
    scatter_k<<<eb4, 256>>>(ei, E, N);
    gemm1_k<<<(N + 127) / 128, 128>>>(x, W1, N);
    agg1_k<<<(N + 63) / 64, 256>>>(b1, N);
    hops_final_k<<<(N + 255) / 256, 256>>>(Wl, bl, W2, N);
    agg2_k<<<(N + 127) / 128, 256>>>(b2, out, N);
}